// round 1
// baseline (speedup 1.0000x reference)
#include <cuda_runtime.h>

// ---------------------------------------------------------------------------
// FSRGraphConv:
//   acc[dst] += [h[src] | eftr[e]]   (160 feats), cnt[dst] += 1
//   feat_mean = acc / max(cnt,1)
//   out = h_dst @ W1^T + feat_mean @ (weight @ W2^T) + (W_b + bias)
// where W1 = W_w[:, :128], W2 = W_w[:, 128:256].
// Fused into: one scatter + one 50000x288x128 fp32 GEMM.
// ---------------------------------------------------------------------------

#define IN_F   128
#define E_F    32
#define FEAT   160   // IN_F + E_F
#define OUT_F  128
#define KTOT   288   // IN_F (h_dst) + FEAT (feat_mean)
#define MAX_NODES 50000

// scratch (static __device__ — no allocations allowed)
__device__ float g_acc[(size_t)MAX_NODES * FEAT];   // 32 MB
__device__ float g_cnt[MAX_NODES];
__device__ float g_Wc[FEAT * OUT_F];    // weight @ W2^T   (160 x 128)
__device__ float g_W1t[IN_F * OUT_F];   // W1 transposed:  W1t[k][o] = W_w[o][k]

// ---------------------------------------------------------------------------
__global__ void zero_kernel(int n_nodes) {
    size_t tid    = (size_t)blockIdx.x * blockDim.x + threadIdx.x;
    size_t stride = (size_t)gridDim.x * blockDim.x;
    size_t n4 = ((size_t)n_nodes * FEAT) / 4;   // 160 divisible by 4
    float4* a4 = reinterpret_cast<float4*>(g_acc);
    float4 z = make_float4(0.f, 0.f, 0.f, 0.f);
    for (size_t i = tid; i < n4; i += stride) a4[i] = z;
    for (size_t i = tid; i < (size_t)n_nodes; i += stride) g_cnt[i] = 0.f;
}

// g_Wc[k][o] = sum_c weight[k][c] * W_w[o][128+c]
// one block per k (160 blocks), 128 threads (thread = o)
__global__ void prep_wc_kernel(const float* __restrict__ weight,
                               const float* __restrict__ W_w) {
    __shared__ float wrow[OUT_F];
    int k = blockIdx.x;
    int o = threadIdx.x;
    wrow[o] = weight[k * OUT_F + o];
    __syncthreads();
    const float* wr = W_w + (size_t)o * (IN_F + OUT_F) + IN_F;
    float s = 0.f;
#pragma unroll 4
    for (int c = 0; c < OUT_F; c++) s = fmaf(wrow[c], wr[c], s);
    g_Wc[k * OUT_F + o] = s;
}

// g_W1t[k][o] = W_w[o][k]   (k,o in [0,128))
__global__ void prep_w1t_kernel(const float* __restrict__ W_w) {
    int idx = blockIdx.x * blockDim.x + threadIdx.x;   // 16384 total
    if (idx < IN_F * OUT_F) {
        int k = idx >> 7;        // /128
        int o = idx & 127;
        g_W1t[idx] = W_w[(size_t)o * (IN_F + OUT_F) + k];
    }
}

// ---------------------------------------------------------------------------
// scatter: one warp per edge (grid-strided).
// lane loads float4 of h[src] (coalesced 128B) -> 4 atomics into acc[dst][0:128]
// lane loads 1 float of eftr[e]               -> 1 atomic into acc[dst][128:160]
__global__ void scatter_kernel(const float* __restrict__ h,
                               const float* __restrict__ eftr,
                               const int*   __restrict__ src_idx,
                               const int*   __restrict__ dst_idx,
                               int n_edges) {
    int lane   = threadIdx.x & 31;
    int warp   = (blockIdx.x * blockDim.x + threadIdx.x) >> 5;
    int nwarps = (gridDim.x * blockDim.x) >> 5;

    for (int e = warp; e < n_edges; e += nwarps) {
        int s = src_idx[e];
        int d = dst_idx[e];
        const float4* hrow = reinterpret_cast<const float4*>(h + (size_t)s * IN_F);
        float4 v = hrow[lane];
        float* arow = g_acc + (size_t)d * FEAT;
        atomicAdd(arow + lane * 4 + 0, v.x);
        atomicAdd(arow + lane * 4 + 1, v.y);
        atomicAdd(arow + lane * 4 + 2, v.z);
        atomicAdd(arow + lane * 4 + 3, v.w);
        float ev = eftr[(size_t)e * E_F + lane];
        atomicAdd(arow + IN_F + lane, ev);
        if (lane == 0) atomicAdd(&g_cnt[d], 1.0f);
    }
}

// ---------------------------------------------------------------------------
// fused GEMM: out[m][o] = sum_{k<128} h[m][k]*W1t[k][o]
//                       + sum_{k<160} (acc[m][k]/denom[m])*Wc[k][o]
//                       + W_b[o] + bias[o]
// BM=64, BN=128, BK=32 (9 chunks: 4 from h, 5 from acc). 256 threads,
// thread (tx,ty): tx in [0,16) -> 8 outputs, ty in [0,16) -> 4 nodes.
__global__ void gemm_kernel(const float* __restrict__ h,
                            const float* __restrict__ W_b,
                            const float* __restrict__ bias,
                            float* __restrict__ out,
                            int n_nodes) {
    __shared__ float Xs[64][33];      // padded: conflict-free
    __shared__ float Ws[32][128];
    __shared__ float sden[64];

    int m0 = blockIdx.x * 64;
    int t  = threadIdx.x;
    int tx = t & 15;        // output tile
    int ty = t >> 4;        // node tile

    if (t < 64) {
        int node = m0 + t;
        float c = (node < n_nodes) ? g_cnt[node] : 1.f;
        sden[t] = 1.f / fmaxf(c, 1.f);
    }
    __syncthreads();

    float acc[4][8];
#pragma unroll
    for (int i = 0; i < 4; i++)
#pragma unroll
        for (int j = 0; j < 8; j++) acc[i][j] = 0.f;

    for (int kc = 0; kc < 9; kc++) {
        // --- load X tile: 64 x 32 ---
#pragma unroll
        for (int i = 0; i < 8; i++) {
            int idx = t + i * 256;          // 0..2047
            int m   = idx >> 5;
            int kk  = idx & 31;
            int node = m0 + m;
            float v = 0.f;
            if (node < n_nodes) {
                if (kc < 4) {
                    v = h[(size_t)node * IN_F + kc * 32 + kk];
                } else {
                    v = g_acc[(size_t)node * FEAT + (kc - 4) * 32 + kk] * sden[m];
                }
            }
            Xs[m][kk] = v;
        }
        // --- load W tile: 32 x 128 (coalesced from W1t / Wc) ---
        const float* Wsrc = (kc < 4) ? (g_W1t + kc * 32 * OUT_F)
                                     : (g_Wc + (kc - 4) * 32 * OUT_F);
#pragma unroll
        for (int i = 0; i < 16; i++) {
            int idx = t + i * 256;          // 0..4095
            Ws[idx >> 7][idx & 127] = Wsrc[idx];
        }
        __syncthreads();

#pragma unroll
        for (int kk = 0; kk < 32; kk++) {
            float xv[4];
#pragma unroll
            for (int i = 0; i < 4; i++) xv[i] = Xs[ty * 4 + i][kk];
            float4 w0 = *reinterpret_cast<const float4*>(&Ws[kk][tx * 8]);
            float4 w1 = *reinterpret_cast<const float4*>(&Ws[kk][tx * 8 + 4]);
#pragma unroll
            for (int i = 0; i < 4; i++) {
                acc[i][0] = fmaf(xv[i], w0.x, acc[i][0]);
                acc[i][1] = fmaf(xv[i], w0.y, acc[i][1]);
                acc[i][2] = fmaf(xv[i], w0.z, acc[i][2]);
                acc[i][3] = fmaf(xv[i], w0.w, acc[i][3]);
                acc[i][4] = fmaf(xv[i], w1.x, acc[i][4]);
                acc[i][5] = fmaf(xv[i], w1.y, acc[i][5]);
                acc[i][6] = fmaf(xv[i], w1.z, acc[i][6]);
                acc[i][7] = fmaf(xv[i], w1.w, acc[i][7]);
            }
        }
        __syncthreads();
    }

    // epilogue
    float bv[8];
#pragma unroll
    for (int j = 0; j < 8; j++) {
        int o = tx * 8 + j;
        bv[j] = W_b[o] + bias[o];
    }
#pragma unroll
    for (int i = 0; i < 4; i++) {
        int node = m0 + ty * 4 + i;
        if (node < n_nodes) {
            float* orow = out + (size_t)node * OUT_F + tx * 8;
#pragma unroll
            for (int j = 0; j < 8; j++) orow[j] = acc[i][j] + bv[j];
        }
    }
}

// ---------------------------------------------------------------------------
extern "C" void kernel_launch(void* const* d_in, const int* in_sizes, int n_in,
                              void* d_out, int out_size) {
    const float* h      = (const float*)d_in[0];
    const float* eftr   = (const float*)d_in[1];
    const float* weight = (const float*)d_in[2];
    const float* W_w    = (const float*)d_in[3];
    const float* W_b    = (const float*)d_in[4];
    const float* bias   = (const float*)d_in[5];
    const int*   src    = (const int*)d_in[6];
    const int*   dst    = (const int*)d_in[7];
    float* out = (float*)d_out;

    int n_nodes = in_sizes[0] / IN_F;
    int n_edges = in_sizes[7];

    zero_kernel<<<1024, 256>>>(n_nodes);
    prep_wc_kernel<<<FEAT, OUT_F>>>(weight, W_w);
    prep_w1t_kernel<<<(IN_F * OUT_F + 255) / 256, 256>>>(W_w);
    scatter_kernel<<<2048, 256>>>(h, eftr, src, dst, n_edges);
    gemm_kernel<<<(n_nodes + 63) / 64, 256>>>(h, W_b, bias, out, n_nodes);
}

// round 2
// speedup vs baseline: 1.6223x; 1.6223x over previous
#include <cuda_runtime.h>

// ---------------------------------------------------------------------------
// FSRGraphConv:
//   acc[dst] += [h[src] | eftr[e]]   (160 feats), cnt[dst] += 1
//   feat_mean = acc / max(cnt,1)
//   out = h_dst @ W1^T + feat_mean @ (weight @ W2^T) + (W_b + bias)
// where W1 = W_w[:, :128], W2 = W_w[:, 128:256].
// Fused into: one scatter (v4 vector atomics) + one 50000x288x128 fp32 GEMM.
// ---------------------------------------------------------------------------

#define IN_F   128
#define E_F    32
#define FEAT   160   // IN_F + E_F
#define OUT_F  128
#define MAX_NODES 50000

// scratch (static __device__ — no allocations allowed)
__device__ __align__(16) float g_acc[(size_t)MAX_NODES * FEAT];   // 32 MB
__device__ float g_cnt[MAX_NODES];
__device__ __align__(16) float g_Wc[FEAT * OUT_F];    // weight @ W2^T (160x128)
__device__ __align__(16) float g_W1t[IN_F * OUT_F];   // W1t[k][o] = W_w[o][k]

// ---------------------------------------------------------------------------
__global__ void zero_kernel(int n_nodes) {
    size_t tid    = (size_t)blockIdx.x * blockDim.x + threadIdx.x;
    size_t stride = (size_t)gridDim.x * blockDim.x;
    size_t n4 = ((size_t)n_nodes * FEAT) / 4;
    float4* a4 = reinterpret_cast<float4*>(g_acc);
    float4 z = make_float4(0.f, 0.f, 0.f, 0.f);
    for (size_t i = tid; i < n4; i += stride) a4[i] = z;
    for (size_t i = tid; i < (size_t)n_nodes; i += stride) g_cnt[i] = 0.f;
}

// g_Wc[k][o] = sum_c weight[k][c] * W_w[o][128+c]
__global__ void prep_wc_kernel(const float* __restrict__ weight,
                               const float* __restrict__ W_w) {
    __shared__ float wrow[OUT_F];
    int k = blockIdx.x;
    int o = threadIdx.x;
    wrow[o] = weight[k * OUT_F + o];
    __syncthreads();
    const float* wr = W_w + (size_t)o * (IN_F + OUT_F) + IN_F;
    float s = 0.f;
#pragma unroll 4
    for (int c = 0; c < OUT_F; c++) s = fmaf(wrow[c], wr[c], s);
    g_Wc[k * OUT_F + o] = s;
}

// g_W1t[k][o] = W_w[o][k]
__global__ void prep_w1t_kernel(const float* __restrict__ W_w) {
    int idx = blockIdx.x * blockDim.x + threadIdx.x;
    if (idx < IN_F * OUT_F) {
        int k = idx >> 7;
        int o = idx & 127;
        g_W1t[idx] = W_w[(size_t)o * (IN_F + OUT_F) + k];
    }
}

// ---------------------------------------------------------------------------
// scatter: one warp per edge. Vector reductions (red.global.add.v4.f32):
// 32 v4-REDs for h row + 8 v4-REDs for eftr row + 1 scalar cnt per edge.
__device__ __forceinline__ void red_v4(float* p, float4 v) {
    asm volatile("red.global.add.v4.f32 [%0], {%1, %2, %3, %4};"
                 :: "l"(p), "f"(v.x), "f"(v.y), "f"(v.z), "f"(v.w)
                 : "memory");
}

__global__ void scatter_kernel(const float* __restrict__ h,
                               const float* __restrict__ eftr,
                               const int*   __restrict__ src_idx,
                               const int*   __restrict__ dst_idx,
                               int n_edges) {
    int lane   = threadIdx.x & 31;
    int warp   = (blockIdx.x * blockDim.x + threadIdx.x) >> 5;
    int nwarps = (gridDim.x * blockDim.x) >> 5;

    for (int e = warp; e < n_edges; e += nwarps) {
        int s = src_idx[e];
        int d = dst_idx[e];
        float4 v = reinterpret_cast<const float4*>(h + (size_t)s * IN_F)[lane];
        float* arow = g_acc + (size_t)d * FEAT;
        red_v4(arow + lane * 4, v);
        if (lane < 8) {
            float4 ev = reinterpret_cast<const float4*>(eftr + (size_t)e * E_F)[lane];
            red_v4(arow + IN_F + lane * 4, ev);
        }
        if (lane == 0) atomicAdd(&g_cnt[d], 1.0f);
    }
}

// ---------------------------------------------------------------------------
// fused GEMM: out[m][o] = sum_{k<128} h[m][k]*W1t[k][o]
//                       + sum_{k<160} (acc[m][k]/denom[m])*Wc[k][o] + W_b[o] + bias[o]
// BM=128, BN=128, BK=16 (18 chunks: 8 from h, 10 from acc). 256 threads, 8x8/thread.
#define BM 128
#define BN 128
#define BK 16

__global__ void gemm_kernel(const float* __restrict__ h,
                            const float* __restrict__ W_b,
                            const float* __restrict__ bias,
                            float* __restrict__ out,
                            int n_nodes) {
    __shared__ float Xs[BK][BM + 4];   // k-major, padded (132 floats/row, 16B-mult)
    __shared__ float Ws[BK][BN];
    __shared__ float sden[BM];

    int m0 = blockIdx.x * BM;
    int t  = threadIdx.x;
    int tx = t & 15;        // output-col tile
    int ty = t >> 4;        // node-row tile

    if (t < BM) {
        int node = m0 + t;
        float c = (node < n_nodes) ? g_cnt[node] : 1.f;
        sden[t] = 1.f / fmaxf(c, 1.f);
    }
    __syncthreads();

    float acc[8][8];
#pragma unroll
    for (int i = 0; i < 8; i++)
#pragma unroll
        for (int j = 0; j < 8; j++) acc[i][j] = 0.f;

    for (int kc = 0; kc < 18; kc++) {
        // --- load X tile (128 x 16): 512 float4s, 2 per thread, store k-major ---
#pragma unroll
        for (int i = 0; i < 2; i++) {
            int idx = t + i * 256;      // 0..511
            int m   = idx >> 2;
            int k4  = idx & 3;
            int node = m0 + m;
            float4 v = make_float4(0.f, 0.f, 0.f, 0.f);
            if (node < n_nodes) {
                if (kc < 8) {
                    v = *reinterpret_cast<const float4*>(
                            h + (size_t)node * IN_F + kc * BK + k4 * 4);
                } else {
                    v = *reinterpret_cast<const float4*>(
                            g_acc + (size_t)node * FEAT + (kc - 8) * BK + k4 * 4);
                    float dn = sden[m];
                    v.x *= dn; v.y *= dn; v.z *= dn; v.w *= dn;
                }
            }
            Xs[k4 * 4 + 0][m] = v.x;
            Xs[k4 * 4 + 1][m] = v.y;
            Xs[k4 * 4 + 2][m] = v.z;
            Xs[k4 * 4 + 3][m] = v.w;
        }
        // --- load W tile (16 x 128): 512 float4s, 2 per thread, coalesced ---
        const float* Wsrc = (kc < 8) ? (g_W1t + kc * BK * OUT_F)
                                     : (g_Wc + (kc - 8) * BK * OUT_F);
#pragma unroll
        for (int i = 0; i < 2; i++) {
            int idx = t + i * 256;      // 0..511
            int k   = idx >> 5;
            int n4  = idx & 31;
            *reinterpret_cast<float4*>(&Ws[k][n4 * 4]) =
                *reinterpret_cast<const float4*>(Wsrc + k * OUT_F + n4 * 4);
        }
        __syncthreads();

#pragma unroll
        for (int kk = 0; kk < BK; kk++) {
            float4 x0 = *reinterpret_cast<const float4*>(&Xs[kk][ty * 8]);
            float4 x1 = *reinterpret_cast<const float4*>(&Xs[kk][ty * 8 + 4]);
            float4 w0 = *reinterpret_cast<const float4*>(&Ws[kk][tx * 8]);
            float4 w1 = *reinterpret_cast<const float4*>(&Ws[kk][tx * 8 + 4]);
            float xv[8] = {x0.x, x0.y, x0.z, x0.w, x1.x, x1.y, x1.z, x1.w};
            float wv[8] = {w0.x, w0.y, w0.z, w0.w, w1.x, w1.y, w1.z, w1.w};
#pragma unroll
            for (int i = 0; i < 8; i++)
#pragma unroll
                for (int j = 0; j < 8; j++)
                    acc[i][j] = fmaf(xv[i], wv[j], acc[i][j]);
        }
        __syncthreads();
    }

    // epilogue
    float bv[8];
#pragma unroll
    for (int j = 0; j < 8; j++) {
        int o = tx * 8 + j;
        bv[j] = W_b[o] + bias[o];
    }
#pragma unroll
    for (int i = 0; i < 8; i++) {
        int node = m0 + ty * 8 + i;
        if (node < n_nodes) {
            float* orow = out + (size_t)node * OUT_F + tx * 8;
            float4 r0 = make_float4(acc[i][0] + bv[0], acc[i][1] + bv[1],
                                    acc[i][2] + bv[2], acc[i][3] + bv[3]);
            float4 r1 = make_float4(acc[i][4] + bv[4], acc[i][5] + bv[5],
                                    acc[i][6] + bv[6], acc[i][7] + bv[7]);
            *reinterpret_cast<float4*>(orow)     = r0;
            *reinterpret_cast<float4*>(orow + 4) = r1;
        }
    }
}

// ---------------------------------------------------------------------------
extern "C" void kernel_launch(void* const* d_in, const int* in_sizes, int n_in,
                              void* d_out, int out_size) {
    const float* h      = (const float*)d_in[0];
    const float* eftr   = (const float*)d_in[1];
    const float* weight = (const float*)d_in[2];
    const float* W_w    = (const float*)d_in[3];
    const float* W_b    = (const float*)d_in[4];
    const float* bias   = (const float*)d_in[5];
    const int*   src    = (const int*)d_in[6];
    const int*   dst    = (const int*)d_in[7];
    float* out = (float*)d_out;

    int n_nodes = in_sizes[0] / IN_F;
    int n_edges = in_sizes[7];

    zero_kernel<<<1024, 256>>>(n_nodes);
    prep_wc_kernel<<<FEAT, OUT_F>>>(weight, W_w);
    prep_w1t_kernel<<<(IN_F * OUT_F + 255) / 256, 256>>>(W_w);
    scatter_kernel<<<2048, 256>>>(h, eftr, src, dst, n_edges);
    gemm_kernel<<<(n_nodes + BM - 1) / BM, 256>>>(h, W_b, bias, out, n_nodes);
}